// round 7
// baseline (speedup 1.0000x reference)
#include <cuda_runtime.h>

#define H  2048
#define SW 256
#define SD 200
#define O  128
#define IH (H + SW)   // 2304

// K2 block layout
#define NB_GRU2 256          // 8 rows per block (warp per row)
#define NB_STK2 50           // 4 depth rows per block
#define NB_DEC2 16           // 8 decoder rows per block (warp per row)

// ---- scratch (device globals) ----
__device__ float g_logits[3];
__device__ float g_sin[SW];
__device__ float g_pr[H];    // Wih_r[:H]·x + Whh_r·h
__device__ float g_pz[H];
__device__ float g_pgin[H];  // Wih_n[:H]·x
__device__ float g_pghn[H];  // Whh_n·h
__device__ float g_hnew[H];
__device__ int   g_done;

__device__ __forceinline__ float dot4(float4 a, float4 b) {
    return a.x*b.x + a.y*b.y + a.z*b.z + a.w*b.w;
}

__device__ __forceinline__ void softmax3_cached(float& pp, float& po, float& pn) {
    float l0 = g_logits[0], l1 = g_logits[1], l2 = g_logits[2];
    float m  = fmaxf(l0, fmaxf(l1, l2));
    float e0 = __expf(l0 - m), e1 = __expf(l1 - m), e2 = __expf(l2 - m);
    float inv = 1.0f / (e0 + e1 + e2);
    pp = e0 * inv; po = e1 * inv; pn = e2 * inv;
}

// =====================================================================
// K1: unchanged (measured ~6 TB/s — at the LTS chip cap).
// blocks [0,2048): GRU main dots (partials). blocks [2048,2307): prologue.
// =====================================================================
__global__ void __launch_bounds__(256) k1_kernel(
    const float* __restrict__ hidden,
    const int*   __restrict__ inp,
    const float* __restrict__ emb,
    const float* __restrict__ W_ih,
    const float* __restrict__ W_hh,
    const float* __restrict__ Wc, const float* __restrict__ bc,
    const float* __restrict__ Ws, const float* __restrict__ bs)
{
    int b = blockIdx.x;
    int t = threadIdx.x;
    const float4* h4 = reinterpret_cast<const float4*>(hidden);
    __shared__ float sm[8][4];
    int lane = t & 31, wid = t >> 5;

    if (b >= 2048) {
        int r = b - 2048;
        const float* rowp = (r < 3) ? (Wc + (size_t)r * H)
                                    : (Ws + (size_t)(r - 3) * H);
        const float4* w4 = reinterpret_cast<const float4*>(rowp);
        float4 a0 = w4[t], a1 = w4[t + 256];
        float4 h0 = h4[t], h1 = h4[t + 256];
        float s = dot4(a0, h0) + dot4(a1, h1);
        #pragma unroll
        for (int o = 16; o > 0; o >>= 1) s += __shfl_down_sync(0xffffffffu, s, o);
        if (lane == 0) sm[wid][0] = s;
        __syncthreads();
        if (t == 0) {
            float S = 0.f;
            #pragma unroll
            for (int j = 0; j < 8; j++) S += sm[j][0];
            if (r < 3) g_logits[r] = S + bc[r];
            else       g_sin[r - 3] = tanhf(S + bs[r - 3]);
            if (r == 0) g_done = 0;   // reset spin counter for K2
        }
        return;
    }

    int i = b;
    const float* x = emb + (size_t)inp[0] * H;
    const float4* x4 = reinterpret_cast<const float4*>(x);
    const float4* wi_r = reinterpret_cast<const float4*>(W_ih + (size_t)i * IH);
    const float4* wi_z = reinterpret_cast<const float4*>(W_ih + (size_t)(H + i) * IH);
    const float4* wi_n = reinterpret_cast<const float4*>(W_ih + (size_t)(2 * H + i) * IH);
    const float4* wh_r = reinterpret_cast<const float4*>(W_hh + (size_t)i * H);
    const float4* wh_z = reinterpret_cast<const float4*>(W_hh + (size_t)(H + i) * H);
    const float4* wh_n = reinterpret_cast<const float4*>(W_hh + (size_t)(2 * H + i) * H);

    float pr = 0.f, pz = 0.f, pgin = 0.f, pghn = 0.f;
    #pragma unroll
    for (int u = 0; u < 2; u++) {
        int k = t + u * 256;
        float4 xv = x4[k];
        float4 hv = h4[k];
        float4 a;
        a = wi_r[k]; pr   += dot4(a, xv);
        a = wh_r[k]; pr   += dot4(a, hv);
        a = wi_z[k]; pz   += dot4(a, xv);
        a = wh_z[k]; pz   += dot4(a, hv);
        a = wi_n[k]; pgin += dot4(a, xv);
        a = wh_n[k]; pghn += dot4(a, hv);
    }

    #pragma unroll
    for (int o = 16; o > 0; o >>= 1) {
        pr   += __shfl_down_sync(0xffffffffu, pr,   o);
        pz   += __shfl_down_sync(0xffffffffu, pz,   o);
        pgin += __shfl_down_sync(0xffffffffu, pgin, o);
        pghn += __shfl_down_sync(0xffffffffu, pghn, o);
    }
    if (lane == 0) { sm[wid][0]=pr; sm[wid][1]=pz; sm[wid][2]=pgin; sm[wid][3]=pghn; }
    __syncthreads();
    if (t < 4) {
        float v = 0.f;
        #pragma unroll
        for (int j = 0; j < 8; j++) v += sm[j][t];
        if      (t == 0) g_pr[i]   = v;
        else if (t == 1) g_pz[i]   = v;
        else if (t == 2) g_pgin[i] = v;
        else             g_pghn[i] = v;
    }
}

// =====================================================================
// K2: 322 blocks x 256 threads — one co-resident wave, warp-autonomous.
//   blocks [0,256):    GRU finish, warp per row (8 rows/block)
//   blocks [256,306):  stack update (4 depth rows/block)
//   blocks [306,322):  decoder, warp per row (spin on g_done==256)
// =====================================================================
__global__ void __launch_bounds__(256) k2_kernel(
    const float* __restrict__ hidden,
    const float* __restrict__ W_ih,
    const float* __restrict__ b_ih, const float* __restrict__ b_hh,
    const float* __restrict__ stack,
    const float* __restrict__ Wd, const float* __restrict__ bd,
    float* __restrict__ out_o, float* __restrict__ out_h,
    float* __restrict__ out_stack)
{
    int b = blockIdx.x;
    int t = threadIdx.x;
    int lane = t & 31, wid = t >> 5;

    if (b < NB_GRU2) {
        // ---------- GRU finish: warp `wid` owns row i ----------
        int i = 8 * b + wid;
        float pp, po, pn; softmax3_cached(pp, po, pn);

        const float4* s0p = reinterpret_cast<const float4*>(stack);
        const float4* s1p = reinterpret_cast<const float4*>(stack + SW);
        const float4* sip = reinterpret_cast<const float4*>(g_sin);
        // two float4 chunks per lane: k and k+32 (covers 64 float4 = SW)
        float4 v00 = s0p[lane],      v10 = s1p[lane],      vs0 = sip[lane];
        float4 v01 = s0p[lane + 32], v11 = s1p[lane + 32], vs1 = sip[lane + 32];
        float4 st0, st1;
        st0.x = pn*v00.x + pp*vs0.x + po*v10.x;
        st0.y = pn*v00.y + pp*vs0.y + po*v10.y;
        st0.z = pn*v00.z + pp*vs0.z + po*v10.z;
        st0.w = pn*v00.w + pp*vs0.w + po*v10.w;
        st1.x = pn*v01.x + pp*vs1.x + po*v11.x;
        st1.y = pn*v01.y + pp*vs1.y + po*v11.y;
        st1.z = pn*v01.z + pp*vs1.z + po*v11.z;
        st1.w = pn*v01.w + pp*vs1.w + po*v11.w;

        const float4* wr = reinterpret_cast<const float4*>(W_ih + (size_t)i * IH + H);
        const float4* wz = reinterpret_cast<const float4*>(W_ih + (size_t)(H + i) * IH + H);
        const float4* wn = reinterpret_cast<const float4*>(W_ih + (size_t)(2 * H + i) * IH + H);
        float ar = dot4(wr[lane], st0) + dot4(wr[lane + 32], st1);
        float az = dot4(wz[lane], st0) + dot4(wz[lane + 32], st1);
        float an = dot4(wn[lane], st0) + dot4(wn[lane + 32], st1);

        #pragma unroll
        for (int o = 16; o > 0; o >>= 1) {
            ar += __shfl_down_sync(0xffffffffu, ar, o);
            az += __shfl_down_sync(0xffffffffu, az, o);
            an += __shfl_down_sync(0xffffffffu, an, o);
        }
        if (lane == 0) {
            float r = 1.0f / (1.0f + expf(-(g_pr[i] + ar + b_ih[i] + b_hh[i])));
            float z = 1.0f / (1.0f + expf(-(g_pz[i] + az + b_ih[H + i] + b_hh[H + i])));
            float n = tanhf(g_pgin[i] + an + b_ih[2 * H + i]
                            + r * (g_pghn[i] + b_hh[2 * H + i]));
            float hn = (1.0f - z) * n + z * hidden[i];
            out_h[i]  = hn;
            g_hnew[i] = hn;
            __threadfence();   // publish g_hnew before block's done-signal
        }
        __syncthreads();
        if (t == 0) atomicAdd(&g_done, 1);   // 256 total, not 2048
        return;
    }

    if (b < NB_GRU2 + NB_STK2) {
        // ---------- stack update: 4 depth rows per block ----------
        int d = 4 * (b - NB_GRU2) + (t >> 6);
        int c = t & 63;
        float pp, po, pn; softmax3_cached(pp, po, pn);
        float4 cur = reinterpret_cast<const float4*>(stack + (size_t)d * SW)[c];
        float4 down = make_float4(0.f, 0.f, 0.f, 0.f);
        if (d < SD - 1)
            down = reinterpret_cast<const float4*>(stack + (size_t)(d + 1) * SW)[c];
        float4 up = (d == 0)
            ? reinterpret_cast<const float4*>(g_sin)[c]
            : reinterpret_cast<const float4*>(stack + (size_t)(d - 1) * SW)[c];
        float4 o;
        o.x = pn*cur.x + pp*up.x + po*down.x;
        o.y = pn*cur.y + pp*up.y + po*down.y;
        o.z = pn*cur.z + pp*up.z + po*down.z;
        o.w = pn*cur.w + pp*up.w + po*down.w;
        reinterpret_cast<float4*>(out_stack)[(size_t)d * (SW / 4) + c] = o;
        return;
    }

    // ---------- decoder: warp per row ----------
    {
        int row = 8 * (b - NB_GRU2 - NB_STK2) + wid;
        if (t == 0) {
            while (atomicAdd(&g_done, 0) < NB_GRU2) __nanosleep(64);
        }
        __syncthreads();
        __threadfence();   // acquire side

        const float4* w4  = reinterpret_cast<const float4*>(Wd + (size_t)row * H);
        const float4* hn4 = reinterpret_cast<const float4*>(g_hnew);
        float s = 0.f;
        #pragma unroll
        for (int u = 0; u < 16; u++) {
            int k = lane + u * 32;
            float4 a  = w4[k];
            float4 hv = __ldcg(hn4 + k);   // written intra-kernel by other SMs
            s += dot4(a, hv);
        }
        #pragma unroll
        for (int o = 16; o > 0; o >>= 1) s += __shfl_down_sync(0xffffffffu, s, o);
        if (lane == 0) out_o[row] = s + bd[row];
    }
}

extern "C" void kernel_launch(void* const* d_in, const int* in_sizes, int n_in,
                              void* d_out, int out_size) {
    const int*   inp    = (const int*)  d_in[0];
    const float* hidden = (const float*)d_in[1];
    const float* stack  = (const float*)d_in[2];
    const float* emb    = (const float*)d_in[3];
    const float* Wc     = (const float*)d_in[4];
    const float* bc     = (const float*)d_in[5];
    const float* Ws     = (const float*)d_in[6];
    const float* bs     = (const float*)d_in[7];
    const float* W_ih   = (const float*)d_in[8];
    const float* b_ih   = (const float*)d_in[9];
    const float* W_hh   = (const float*)d_in[10];
    const float* b_hh   = (const float*)d_in[11];
    const float* Wd     = (const float*)d_in[12];
    const float* bd     = (const float*)d_in[13];

    float* out       = (float*)d_out;
    float* out_o     = out;            // (1,O)     : 128
    float* out_h     = out + O;        // (1,1,H)   : 2048
    float* out_stack = out + O + H;    // (1,SD,SW) : 51200

    k1_kernel<<<2048 + 3 + SW, 256>>>(hidden, inp, emb, W_ih, W_hh,
                                      Wc, bc, Ws, bs);
    k2_kernel<<<NB_GRU2 + NB_STK2 + NB_DEC2, 256>>>(
        hidden, W_ih, b_ih, b_hh, stack, Wd, bd, out_o, out_h, out_stack);
}

// round 8
// speedup vs baseline: 1.1333x; 1.1333x over previous
#include <cuda_runtime.h>

#define H  2048
#define SW 256
#define SD 200
#define O  128
#define IH (H + SW)   // 2304

// K2a block layout
#define NB_GRU2 256          // 8 rows per block (warp per row)
#define NB_STK2 50           // 4 depth rows per block

// ---- scratch (device globals) ----
__device__ float g_logits[3];
__device__ float g_sin[SW];
__device__ float g_pr[H];    // Wih_r[:H]·x + Whh_r·h
__device__ float g_pz[H];
__device__ float g_pgin[H];  // Wih_n[:H]·x
__device__ float g_pghn[H];  // Whh_n·h
__device__ float g_hnew[H];

__device__ __forceinline__ float dot4(float4 a, float4 b) {
    return a.x*b.x + a.y*b.y + a.z*b.z + a.w*b.w;
}

__device__ __forceinline__ void softmax3_cached(float& pp, float& po, float& pn) {
    float l0 = g_logits[0], l1 = g_logits[1], l2 = g_logits[2];
    float m  = fmaxf(l0, fmaxf(l1, l2));
    float e0 = __expf(l0 - m), e1 = __expf(l1 - m), e2 = __expf(l2 - m);
    float inv = 1.0f / (e0 + e1 + e2);
    pp = e0 * inv; po = e1 * inv; pn = e2 * inv;
}

// =====================================================================
// K1: unchanged (measured ~6 TB/s).
// blocks [0,2048): GRU main dots (partials). blocks [2048,2307): prologue.
// =====================================================================
__global__ void __launch_bounds__(256) k1_kernel(
    const float* __restrict__ hidden,
    const int*   __restrict__ inp,
    const float* __restrict__ emb,
    const float* __restrict__ W_ih,
    const float* __restrict__ W_hh,
    const float* __restrict__ Wc, const float* __restrict__ bc,
    const float* __restrict__ Ws, const float* __restrict__ bs)
{
    int b = blockIdx.x;
    int t = threadIdx.x;
    const float4* h4 = reinterpret_cast<const float4*>(hidden);
    __shared__ float sm[8][4];
    int lane = t & 31, wid = t >> 5;

    if (b >= 2048) {
        int r = b - 2048;
        const float* rowp = (r < 3) ? (Wc + (size_t)r * H)
                                    : (Ws + (size_t)(r - 3) * H);
        const float4* w4 = reinterpret_cast<const float4*>(rowp);
        float4 a0 = w4[t], a1 = w4[t + 256];
        float4 h0 = h4[t], h1 = h4[t + 256];
        float s = dot4(a0, h0) + dot4(a1, h1);
        #pragma unroll
        for (int o = 16; o > 0; o >>= 1) s += __shfl_down_sync(0xffffffffu, s, o);
        if (lane == 0) sm[wid][0] = s;
        __syncthreads();
        if (t == 0) {
            float S = 0.f;
            #pragma unroll
            for (int j = 0; j < 8; j++) S += sm[j][0];
            if (r < 3) g_logits[r] = S + bc[r];
            else       g_sin[r - 3] = tanhf(S + bs[r - 3]);
        }
        return;
    }

    int i = b;
    const float* x = emb + (size_t)inp[0] * H;
    const float4* x4 = reinterpret_cast<const float4*>(x);
    const float4* wi_r = reinterpret_cast<const float4*>(W_ih + (size_t)i * IH);
    const float4* wi_z = reinterpret_cast<const float4*>(W_ih + (size_t)(H + i) * IH);
    const float4* wi_n = reinterpret_cast<const float4*>(W_ih + (size_t)(2 * H + i) * IH);
    const float4* wh_r = reinterpret_cast<const float4*>(W_hh + (size_t)i * H);
    const float4* wh_z = reinterpret_cast<const float4*>(W_hh + (size_t)(H + i) * H);
    const float4* wh_n = reinterpret_cast<const float4*>(W_hh + (size_t)(2 * H + i) * H);

    float pr = 0.f, pz = 0.f, pgin = 0.f, pghn = 0.f;
    #pragma unroll
    for (int u = 0; u < 2; u++) {
        int k = t + u * 256;
        float4 xv = x4[k];
        float4 hv = h4[k];
        float4 a;
        a = wi_r[k]; pr   += dot4(a, xv);
        a = wh_r[k]; pr   += dot4(a, hv);
        a = wi_z[k]; pz   += dot4(a, xv);
        a = wh_z[k]; pz   += dot4(a, hv);
        a = wi_n[k]; pgin += dot4(a, xv);
        a = wh_n[k]; pghn += dot4(a, hv);
    }

    #pragma unroll
    for (int o = 16; o > 0; o >>= 1) {
        pr   += __shfl_down_sync(0xffffffffu, pr,   o);
        pz   += __shfl_down_sync(0xffffffffu, pz,   o);
        pgin += __shfl_down_sync(0xffffffffu, pgin, o);
        pghn += __shfl_down_sync(0xffffffffu, pghn, o);
    }
    if (lane == 0) { sm[wid][0]=pr; sm[wid][1]=pz; sm[wid][2]=pgin; sm[wid][3]=pghn; }
    __syncthreads();
    if (t < 4) {
        float v = 0.f;
        #pragma unroll
        for (int j = 0; j < 8; j++) v += sm[j][t];
        if      (t == 0) g_pr[i]   = v;
        else if (t == 1) g_pz[i]   = v;
        else if (t == 2) g_pgin[i] = v;
        else             g_pghn[i] = v;
    }
}

// =====================================================================
// K2a: GRU finish + stack update. NO atomics, NO spins, NO fences.
//   blocks [0,256):    GRU finish, warp per row (8 rows/block)
//   blocks [256,306):  stack update (4 depth rows/block)
// =====================================================================
__global__ void __launch_bounds__(256) k2a_kernel(
    const float* __restrict__ hidden,
    const float* __restrict__ W_ih,
    const float* __restrict__ b_ih, const float* __restrict__ b_hh,
    const float* __restrict__ stack,
    float* __restrict__ out_h, float* __restrict__ out_stack)
{
    int b = blockIdx.x;
    int t = threadIdx.x;
    int lane = t & 31, wid = t >> 5;

    if (b < NB_GRU2) {
        // ---------- GRU finish: warp `wid` owns row i ----------
        int i = 8 * b + wid;

        // hoist lane-0 scalar tail loads to warp start (11 independent LDGs)
        float pr = 0, pz = 0, pgin = 0, pghn = 0;
        float bir = 0, biz = 0, bin_ = 0, bhr = 0, bhz = 0, bhn = 0, hid = 0;
        if (lane == 0) {
            pr  = g_pr[i];   pz  = g_pz[i];
            pgin = g_pgin[i]; pghn = g_pghn[i];
            bir = b_ih[i]; biz = b_ih[H + i]; bin_ = b_ih[2 * H + i];
            bhr = b_hh[i]; bhz = b_hh[H + i]; bhn  = b_hh[2 * H + i];
            hid = hidden[i];
        }

        float pp, po, pn; softmax3_cached(pp, po, pn);

        const float4* s0p = reinterpret_cast<const float4*>(stack);
        const float4* s1p = reinterpret_cast<const float4*>(stack + SW);
        const float4* sip = reinterpret_cast<const float4*>(g_sin);
        float4 v00 = s0p[lane],      v10 = s1p[lane],      vs0 = sip[lane];
        float4 v01 = s0p[lane + 32], v11 = s1p[lane + 32], vs1 = sip[lane + 32];
        float4 st0, st1;
        st0.x = pn*v00.x + pp*vs0.x + po*v10.x;
        st0.y = pn*v00.y + pp*vs0.y + po*v10.y;
        st0.z = pn*v00.z + pp*vs0.z + po*v10.z;
        st0.w = pn*v00.w + pp*vs0.w + po*v10.w;
        st1.x = pn*v01.x + pp*vs1.x + po*v11.x;
        st1.y = pn*v01.y + pp*vs1.y + po*v11.y;
        st1.z = pn*v01.z + pp*vs1.z + po*v11.z;
        st1.w = pn*v01.w + pp*vs1.w + po*v11.w;

        const float4* wr = reinterpret_cast<const float4*>(W_ih + (size_t)i * IH + H);
        const float4* wz = reinterpret_cast<const float4*>(W_ih + (size_t)(H + i) * IH + H);
        const float4* wn = reinterpret_cast<const float4*>(W_ih + (size_t)(2 * H + i) * IH + H);
        float ar = dot4(wr[lane], st0) + dot4(wr[lane + 32], st1);
        float az = dot4(wz[lane], st0) + dot4(wz[lane + 32], st1);
        float an = dot4(wn[lane], st0) + dot4(wn[lane + 32], st1);

        #pragma unroll
        for (int o = 16; o > 0; o >>= 1) {
            ar += __shfl_down_sync(0xffffffffu, ar, o);
            az += __shfl_down_sync(0xffffffffu, az, o);
            an += __shfl_down_sync(0xffffffffu, an, o);
        }
        if (lane == 0) {
            float r = 1.0f / (1.0f + expf(-(pr + ar + bir + bhr)));
            float z = 1.0f / (1.0f + expf(-(pz + az + biz + bhz)));
            float n = tanhf(pgin + an + bin_ + r * (pghn + bhn));
            float hn = (1.0f - z) * n + z * hid;
            out_h[i]  = hn;
            g_hnew[i] = hn;
        }
        return;
    }

    // ---------- stack update: 4 depth rows per block ----------
    {
        int d = 4 * (b - NB_GRU2) + (t >> 6);
        int c = t & 63;
        float pp, po, pn; softmax3_cached(pp, po, pn);
        float4 cur = reinterpret_cast<const float4*>(stack + (size_t)d * SW)[c];
        float4 down = make_float4(0.f, 0.f, 0.f, 0.f);
        if (d < SD - 1)
            down = reinterpret_cast<const float4*>(stack + (size_t)(d + 1) * SW)[c];
        float4 up = (d == 0)
            ? reinterpret_cast<const float4*>(g_sin)[c]
            : reinterpret_cast<const float4*>(stack + (size_t)(d - 1) * SW)[c];
        float4 o;
        o.x = pn*cur.x + pp*up.x + po*down.x;
        o.y = pn*cur.y + pp*up.y + po*down.y;
        o.z = pn*cur.z + pp*up.z + po*down.z;
        o.w = pn*cur.w + pp*up.w + po*down.w;
        reinterpret_cast<float4*>(out_stack)[(size_t)d * (SW / 4) + c] = o;
    }
}

// =====================================================================
// K2b: decoder — out = Wd @ h_new + bd. 128 blocks, 256 threads.
// Reads g_hnew across the kernel boundary (R3-validated pattern).
// =====================================================================
__global__ void __launch_bounds__(256) k2b_kernel(
    const float* __restrict__ Wd, const float* __restrict__ bd,
    float* __restrict__ out_o)
{
    int b = blockIdx.x;
    int t = threadIdx.x;
    const float4* w4 = reinterpret_cast<const float4*>(Wd + (size_t)b * H);
    const float4* h4 = reinterpret_cast<const float4*>(g_hnew);
    float4 a0 = w4[t], a1 = w4[t + 256];
    float4 h0 = h4[t], h1 = h4[t + 256];
    float s = dot4(a0, h0) + dot4(a1, h1);

    __shared__ float sm[8];
    int lane = t & 31, wid = t >> 5;
    #pragma unroll
    for (int o = 16; o > 0; o >>= 1) s += __shfl_down_sync(0xffffffffu, s, o);
    if (lane == 0) sm[wid] = s;
    __syncthreads();
    if (t == 0) {
        float S = 0.f;
        #pragma unroll
        for (int j = 0; j < 8; j++) S += sm[j];
        out_o[b] = S + bd[b];
    }
}

extern "C" void kernel_launch(void* const* d_in, const int* in_sizes, int n_in,
                              void* d_out, int out_size) {
    const int*   inp    = (const int*)  d_in[0];
    const float* hidden = (const float*)d_in[1];
    const float* stack  = (const float*)d_in[2];
    const float* emb    = (const float*)d_in[3];
    const float* Wc     = (const float*)d_in[4];
    const float* bc     = (const float*)d_in[5];
    const float* Ws     = (const float*)d_in[6];
    const float* bs     = (const float*)d_in[7];
    const float* W_ih   = (const float*)d_in[8];
    const float* b_ih   = (const float*)d_in[9];
    const float* W_hh   = (const float*)d_in[10];
    const float* b_hh   = (const float*)d_in[11];
    const float* Wd     = (const float*)d_in[12];
    const float* bd     = (const float*)d_in[13];

    float* out       = (float*)d_out;
    float* out_o     = out;            // (1,O)     : 128
    float* out_h     = out + O;        // (1,1,H)   : 2048
    float* out_stack = out + O + H;    // (1,SD,SW) : 51200

    k1_kernel<<<2048 + 3 + SW, 256>>>(hidden, inp, emb, W_ih, W_hh,
                                      Wc, bc, Ws, bs);
    k2a_kernel<<<NB_GRU2 + NB_STK2, 256>>>(hidden, W_ih, b_ih, b_hh,
                                           stack, out_h, out_stack);
    k2b_kernel<<<O, 256>>>(Wd, bd, out_o);
}

// round 9
// speedup vs baseline: 1.2273x; 1.0830x over previous
#include <cuda_runtime.h>

#define H  2048
#define SW 256
#define SD 200
#define O  128
#define IH (H + SW)   // 2304

#define NB_GRU2 256          // 8 rows per block (warp per row)
#define NB_STK2 50           // 4 depth rows per block

// ---- scratch (device globals) ----
__device__ float g_logits[3];
__device__ float g_sin[SW];
__device__ float g_pr[H];    // Wih_r[:H]·x + Whh_r·h
__device__ float g_pz[H];
__device__ float g_pgin[H];  // Wih_n[:H]·x
__device__ float g_pghn[H];  // Whh_n·h
__device__ float g_hnew[H];

__device__ __forceinline__ float dot4(float4 a, float4 b) {
    return a.x*b.x + a.y*b.y + a.z*b.z + a.w*b.w;
}

// PDL intrinsics
__device__ __forceinline__ void gdc_wait() {
    asm volatile("griddepcontrol.wait;" ::: "memory");
}
__device__ __forceinline__ void gdc_launch_dependents() {
    asm volatile("griddepcontrol.launch_dependents;");
}

__device__ __forceinline__ void softmax3_cached(float& pp, float& po, float& pn) {
    float l0 = g_logits[0], l1 = g_logits[1], l2 = g_logits[2];
    float m  = fmaxf(l0, fmaxf(l1, l2));
    float e0 = __expf(l0 - m), e1 = __expf(l1 - m), e2 = __expf(l2 - m);
    float inv = 1.0f / (e0 + e1 + e2);
    pp = e0 * inv; po = e1 * inv; pn = e2 * inv;
}

// =====================================================================
// K1: blocks [0,2048): GRU main dots (partials). blocks [2048,2307):
// prologue dots. Occupancy forced to 6 blocks/SM.
// =====================================================================
__global__ void __launch_bounds__(256, 6) k1_kernel(
    const float* __restrict__ hidden,
    const int*   __restrict__ inp,
    const float* __restrict__ emb,
    const float* __restrict__ W_ih,
    const float* __restrict__ W_hh,
    const float* __restrict__ Wc, const float* __restrict__ bc,
    const float* __restrict__ Ws, const float* __restrict__ bs)
{
    gdc_launch_dependents();   // let K2a start prefetching early

    int b = blockIdx.x;
    int t = threadIdx.x;
    const float4* h4 = reinterpret_cast<const float4*>(hidden);
    __shared__ float sm[8][4];
    int lane = t & 31, wid = t >> 5;

    if (b >= 2048) {
        int r = b - 2048;
        const float* rowp = (r < 3) ? (Wc + (size_t)r * H)
                                    : (Ws + (size_t)(r - 3) * H);
        const float4* w4 = reinterpret_cast<const float4*>(rowp);
        float4 a0 = w4[t], a1 = w4[t + 256];
        float4 h0 = h4[t], h1 = h4[t + 256];
        float s = dot4(a0, h0) + dot4(a1, h1);
        #pragma unroll
        for (int o = 16; o > 0; o >>= 1) s += __shfl_down_sync(0xffffffffu, s, o);
        if (lane == 0) sm[wid][0] = s;
        __syncthreads();
        if (t == 0) {
            float S = 0.f;
            #pragma unroll
            for (int j = 0; j < 8; j++) S += sm[j][0];
            if (r < 3) g_logits[r] = S + bc[r];
            else       g_sin[r - 3] = tanhf(S + bs[r - 3]);
        }
        return;
    }

    int i = b;
    const float* x = emb + (size_t)inp[0] * H;
    const float4* x4 = reinterpret_cast<const float4*>(x);
    const float4* wi_r = reinterpret_cast<const float4*>(W_ih + (size_t)i * IH);
    const float4* wi_z = reinterpret_cast<const float4*>(W_ih + (size_t)(H + i) * IH);
    const float4* wi_n = reinterpret_cast<const float4*>(W_ih + (size_t)(2 * H + i) * IH);
    const float4* wh_r = reinterpret_cast<const float4*>(W_hh + (size_t)i * H);
    const float4* wh_z = reinterpret_cast<const float4*>(W_hh + (size_t)(H + i) * H);
    const float4* wh_n = reinterpret_cast<const float4*>(W_hh + (size_t)(2 * H + i) * H);

    float pr = 0.f, pz = 0.f, pgin = 0.f, pghn = 0.f;
    #pragma unroll
    for (int u = 0; u < 2; u++) {
        int k = t + u * 256;
        float4 xv = x4[k];
        float4 hv = h4[k];
        float4 a;
        a = wi_r[k]; pr   += dot4(a, xv);
        a = wh_r[k]; pr   += dot4(a, hv);
        a = wi_z[k]; pz   += dot4(a, xv);
        a = wh_z[k]; pz   += dot4(a, hv);
        a = wi_n[k]; pgin += dot4(a, xv);
        a = wh_n[k]; pghn += dot4(a, hv);
    }

    #pragma unroll
    for (int o = 16; o > 0; o >>= 1) {
        pr   += __shfl_down_sync(0xffffffffu, pr,   o);
        pz   += __shfl_down_sync(0xffffffffu, pz,   o);
        pgin += __shfl_down_sync(0xffffffffu, pgin, o);
        pghn += __shfl_down_sync(0xffffffffu, pghn, o);
    }
    if (lane == 0) { sm[wid][0]=pr; sm[wid][1]=pz; sm[wid][2]=pgin; sm[wid][3]=pghn; }
    __syncthreads();
    if (t < 4) {
        float v = 0.f;
        #pragma unroll
        for (int j = 0; j < 8; j++) v += sm[j][t];
        if      (t == 0) g_pr[i]   = v;
        else if (t == 1) g_pz[i]   = v;
        else if (t == 2) g_pgin[i] = v;
        else             g_pghn[i] = v;
    }
}

// =====================================================================
// K2a: GRU finish + stack update. PDL: prefetch independent inputs,
// then griddepcontrol.wait, then read K1 outputs.
// =====================================================================
__global__ void __launch_bounds__(256) k2a_kernel(
    const float* __restrict__ hidden,
    const float* __restrict__ W_ih,
    const float* __restrict__ b_ih, const float* __restrict__ b_hh,
    const float* __restrict__ stack,
    float* __restrict__ out_h, float* __restrict__ out_stack)
{
    gdc_launch_dependents();   // let K2b start prefetching Wd early

    int b = blockIdx.x;
    int t = threadIdx.x;
    int lane = t & 31, wid = t >> 5;

    if (b < NB_GRU2) {
        // ---------- GRU finish: warp `wid` owns row i ----------
        int i = 8 * b + wid;

        // prefetch: independent inputs (weights, biases, stack, hidden)
        const float4* s0p = reinterpret_cast<const float4*>(stack);
        const float4* s1p = reinterpret_cast<const float4*>(stack + SW);
        float4 v00 = s0p[lane],      v10 = s1p[lane];
        float4 v01 = s0p[lane + 32], v11 = s1p[lane + 32];

        const float4* wr = reinterpret_cast<const float4*>(W_ih + (size_t)i * IH + H);
        const float4* wz = reinterpret_cast<const float4*>(W_ih + (size_t)(H + i) * IH + H);
        const float4* wn = reinterpret_cast<const float4*>(W_ih + (size_t)(2 * H + i) * IH + H);
        float4 wr0 = wr[lane], wr1 = wr[lane + 32];
        float4 wz0 = wz[lane], wz1 = wz[lane + 32];
        float4 wn0 = wn[lane], wn1 = wn[lane + 32];

        float bir = 0, biz = 0, bin_ = 0, bhr = 0, bhz = 0, bhn = 0, hid = 0;
        if (lane == 0) {
            bir = b_ih[i]; biz = b_ih[H + i]; bin_ = b_ih[2 * H + i];
            bhr = b_hh[i]; bhz = b_hh[H + i]; bhn  = b_hh[2 * H + i];
            hid = hidden[i];
        }

        gdc_wait();   // K1 outputs now visible

        float pr = 0, pz = 0, pgin = 0, pghn = 0;
        if (lane == 0) {
            pr   = g_pr[i];   pz   = g_pz[i];
            pgin = g_pgin[i]; pghn = g_pghn[i];
        }
        float pp, po, pn; softmax3_cached(pp, po, pn);
        const float4* sip = reinterpret_cast<const float4*>(g_sin);
        float4 vs0 = sip[lane], vs1 = sip[lane + 32];

        float4 st0, st1;
        st0.x = pn*v00.x + pp*vs0.x + po*v10.x;
        st0.y = pn*v00.y + pp*vs0.y + po*v10.y;
        st0.z = pn*v00.z + pp*vs0.z + po*v10.z;
        st0.w = pn*v00.w + pp*vs0.w + po*v10.w;
        st1.x = pn*v01.x + pp*vs1.x + po*v11.x;
        st1.y = pn*v01.y + pp*vs1.y + po*v11.y;
        st1.z = pn*v01.z + pp*vs1.z + po*v11.z;
        st1.w = pn*v01.w + pp*vs1.w + po*v11.w;

        float ar = dot4(wr0, st0) + dot4(wr1, st1);
        float az = dot4(wz0, st0) + dot4(wz1, st1);
        float an = dot4(wn0, st0) + dot4(wn1, st1);

        #pragma unroll
        for (int o = 16; o > 0; o >>= 1) {
            ar += __shfl_down_sync(0xffffffffu, ar, o);
            az += __shfl_down_sync(0xffffffffu, az, o);
            an += __shfl_down_sync(0xffffffffu, an, o);
        }
        if (lane == 0) {
            float r = 1.0f / (1.0f + expf(-(pr + ar + bir + bhr)));
            float z = 1.0f / (1.0f + expf(-(pz + az + biz + bhz)));
            float n = tanhf(pgin + an + bin_ + r * (pghn + bhn));
            float hn = (1.0f - z) * n + z * hid;
            out_h[i]  = hn;
            g_hnew[i] = hn;
        }
        return;
    }

    // ---------- stack update: 4 depth rows per block ----------
    {
        int d = 4 * (b - NB_GRU2) + (t >> 6);
        int c = t & 63;
        // prefetch independent inputs
        float4 cur = reinterpret_cast<const float4*>(stack + (size_t)d * SW)[c];
        float4 down = make_float4(0.f, 0.f, 0.f, 0.f);
        if (d < SD - 1)
            down = reinterpret_cast<const float4*>(stack + (size_t)(d + 1) * SW)[c];
        float4 up = make_float4(0.f, 0.f, 0.f, 0.f);
        if (d > 0)
            up = reinterpret_cast<const float4*>(stack + (size_t)(d - 1) * SW)[c];

        gdc_wait();

        float pp, po, pn; softmax3_cached(pp, po, pn);
        if (d == 0)
            up = reinterpret_cast<const float4*>(g_sin)[c];
        float4 o;
        o.x = pn*cur.x + pp*up.x + po*down.x;
        o.y = pn*cur.y + pp*up.y + po*down.y;
        o.z = pn*cur.z + pp*up.z + po*down.z;
        o.w = pn*cur.w + pp*up.w + po*down.w;
        reinterpret_cast<float4*>(out_stack)[(size_t)d * (SW / 4) + c] = o;
    }
}

// =====================================================================
// K2b: decoder — prefetch Wd, wait, then read g_hnew.
// =====================================================================
__global__ void __launch_bounds__(256) k2b_kernel(
    const float* __restrict__ Wd, const float* __restrict__ bd,
    float* __restrict__ out_o)
{
    int b = blockIdx.x;
    int t = threadIdx.x;
    const float4* w4 = reinterpret_cast<const float4*>(Wd + (size_t)b * H);
    float4 a0 = w4[t], a1 = w4[t + 256];
    float bias = (t == 0) ? bd[b] : 0.f;

    gdc_wait();

    const float4* h4 = reinterpret_cast<const float4*>(g_hnew);
    float4 h0 = h4[t], h1 = h4[t + 256];
    float s = dot4(a0, h0) + dot4(a1, h1);

    __shared__ float sm[8];
    int lane = t & 31, wid = t >> 5;
    #pragma unroll
    for (int o = 16; o > 0; o >>= 1) s += __shfl_down_sync(0xffffffffu, s, o);
    if (lane == 0) sm[wid] = s;
    __syncthreads();
    if (t == 0) {
        float S = 0.f;
        #pragma unroll
        for (int j = 0; j < 8; j++) S += sm[j];
        out_o[b] = S + bias;
    }
}

extern "C" void kernel_launch(void* const* d_in, const int* in_sizes, int n_in,
                              void* d_out, int out_size) {
    const int*   inp    = (const int*)  d_in[0];
    const float* hidden = (const float*)d_in[1];
    const float* stack  = (const float*)d_in[2];
    const float* emb    = (const float*)d_in[3];
    const float* Wc     = (const float*)d_in[4];
    const float* bc     = (const float*)d_in[5];
    const float* Ws     = (const float*)d_in[6];
    const float* bs     = (const float*)d_in[7];
    const float* W_ih   = (const float*)d_in[8];
    const float* b_ih   = (const float*)d_in[9];
    const float* W_hh   = (const float*)d_in[10];
    const float* b_hh   = (const float*)d_in[11];
    const float* Wd     = (const float*)d_in[12];
    const float* bd     = (const float*)d_in[13];

    float* out       = (float*)d_out;
    float* out_o     = out;            // (1,O)     : 128
    float* out_h     = out + O;        // (1,1,H)   : 2048
    float* out_stack = out + O + H;    // (1,SD,SW) : 51200

    // K1: normal launch
    k1_kernel<<<2048 + 3 + SW, 256>>>(hidden, inp, emb, W_ih, W_hh,
                                      Wc, bc, Ws, bs);

    // K2a / K2b: PDL launches (programmatic stream serialization)
    cudaLaunchAttribute attr[1];
    attr[0].id = cudaLaunchAttributeProgrammaticStreamSerialization;
    attr[0].val.programmaticStreamSerializationAllowed = 1;

    {
        cudaLaunchConfig_t cfg = {};
        cfg.gridDim  = dim3(NB_GRU2 + NB_STK2);
        cfg.blockDim = dim3(256);
        cfg.dynamicSmemBytes = 0;
        cfg.stream = 0;
        cfg.attrs = attr;
        cfg.numAttrs = 1;
        cudaLaunchKernelEx(&cfg, k2a_kernel, hidden, W_ih, b_ih, b_hh,
                           stack, out_h, out_stack);
    }
    {
        cudaLaunchConfig_t cfg = {};
        cfg.gridDim  = dim3(O);
        cfg.blockDim = dim3(256);
        cfg.dynamicSmemBytes = 0;
        cfg.stream = 0;
        cfg.attrs = attr;
        cfg.numAttrs = 1;
        cudaLaunchKernelEx(&cfg, k2b_kernel, Wd, bd, out_o);
    }
}